// round 8
// baseline (speedup 1.0000x reference)
#include <cuda_runtime.h>

#define FULL_MASK 0xFFFFFFFFu

constexpr int DATA_THREADS = 256;         // 8 data warps
constexpr int BLOCK = DATA_THREADS + 32;  // + 1 lookback warp
constexpr int ITEMS = 32;                 // per data thread, 8x float4
constexpr int TILE  = DATA_THREADS * ITEMS;  // 8192 floats
constexpr int NDWARPS = DATA_THREADS / 32;   // 8
constexpr int MAX_TILES = 4096;           // 2^25 / 8192

// Lookback descriptors, epoch-tagged so NO clearing pass is needed between
// graph replays. High 32 bits = (epoch << 2) | state, low 32 bits = fp32 bits.
//   state: 0 = invalid, 1 = aggregate, 2 = inclusive.
// Single 64-bit relaxed store publishes tag+value atomically.
__device__ unsigned long long g_status[MAX_TILES];
__device__ unsigned int       g_ticket;   // monotonic across replays, never reset

__device__ __forceinline__ unsigned long long ld_status(const unsigned long long* p) {
    unsigned long long v;
    asm volatile("ld.relaxed.gpu.global.u64 %0, [%1];" : "=l"(v) : "l"(p));
    return v;
}
__device__ __forceinline__ void st_status(unsigned long long* p, unsigned long long v) {
    asm volatile("st.relaxed.gpu.global.u64 [%0], %1;" :: "l"(p), "l"(v) : "memory");
}
__device__ __forceinline__ unsigned long long pack_status(unsigned epoch, unsigned state, float val) {
    return ((unsigned long long)((epoch << 2) | state) << 32)
         | (unsigned long long)__float_as_uint(val);
}
__device__ __forceinline__ void bar_data() {       // named barrier: 256 data threads only
    asm volatile("bar.sync 1, %0;" :: "n"(DATA_THREADS) : "memory");
}

__global__ void __launch_bounds__(BLOCK)
scan_kernel(const float* __restrict__ x, float* __restrict__ out, int n, unsigned ntiles) {
    __shared__ float s_totals[NDWARPS];
    __shared__ float s_excl[NDWARPS];
    __shared__ volatile float    s_agg;
    __shared__ volatile float    s_prefix;
    __shared__ volatile unsigned f_agg;     // data -> warp0: aggregate ready
    __shared__ volatile unsigned f_prefix;  // warp0 -> data: prefix ready
    __shared__ unsigned s_ticket;

    const int tid  = threadIdx.x;
    const int lane = tid & 31;

    if (tid == 0) {
        f_agg = 0u; f_prefix = 0u;
        s_ticket = atomicAdd(&g_ticket, 1u);   // scheduling-ordered tile ids
    }
    __syncthreads();
    const unsigned ticket = s_ticket;
    const unsigned epoch  = ticket / ntiles;
    const unsigned tile   = ticket % ntiles;

    if (tid >= 32) {
        // ================== DATA PATH: 8 warps, 8192 floats ==================
        const int dtid  = tid - 32;
        const int dwarp = dtid >> 5;
        const size_t base = (size_t)tile * TILE + (size_t)dtid * ITEMS;

        float v[ITEMS];
        const bool full_tile = (base + ITEMS) <= (size_t)n;
        if (full_tile) {
            const float4* p = reinterpret_cast<const float4*>(x + base);
            #pragma unroll
            for (int j = 0; j < ITEMS / 4; j++) {
                float4 a = __ldcs(p + j);
                v[4*j+0] = a.x; v[4*j+1] = a.y; v[4*j+2] = a.z; v[4*j+3] = a.w;
            }
        } else {
            #pragma unroll
            for (int i = 0; i < ITEMS; i++)
                v[i] = (base + (size_t)i < (size_t)n) ? x[base + i] : 0.f;
        }

        #pragma unroll
        for (int i = 1; i < ITEMS; i++) v[i] += v[i - 1];
        const float tsum = v[ITEMS - 1];

        float incl = tsum;
        #pragma unroll
        for (int d = 1; d < 32; d <<= 1) {
            float t = __shfl_up_sync(FULL_MASK, incl, d);
            if (lane >= d) incl += t;
        }
        const float texcl = incl - tsum;
        if (lane == 31) s_totals[dwarp] = incl;
        bar_data();

        if (dwarp == 0) {
            float wv = (lane < NDWARPS) ? s_totals[lane] : 0.f;
            float wincl = wv;
            #pragma unroll
            for (int d = 1; d < NDWARPS; d <<= 1) {
                float t = __shfl_up_sync(FULL_MASK, wincl, d);
                if (lane >= d) wincl += t;
            }
            if (lane < NDWARPS) s_excl[lane] = wincl - wv;
            if (lane == NDWARPS - 1) {
                s_agg = wincl;               // block aggregate
                __threadfence_block();
                f_agg = 1u;                  // hand to warp 0 ASAP
            }
        }
        bar_data();                          // s_excl ready for all data warps

        while (f_prefix == 0u) { }           // wait for lookback warp
        const float off = s_prefix + s_excl[dwarp] + texcl;
        #pragma unroll
        for (int i = 0; i < ITEMS; i++) v[i] += off;

        if (full_tile) {
            float4* q = reinterpret_cast<float4*>(out + base);
            #pragma unroll
            for (int j = 0; j < ITEMS / 4; j++)
                __stcs(q + j, make_float4(v[4*j+0], v[4*j+1], v[4*j+2], v[4*j+3]));
        } else {
            #pragma unroll
            for (int i = 0; i < ITEMS; i++)
                if (base + (size_t)i < (size_t)n) out[base + i] = v[i];
        }
    } else {
        // ============ LOOKBACK WARP: walk overlapped with data loads ============
        float prefix = 0.f;
        bool agg_published = false;

        if (tile > 0) {
            int wend = (int)tile;            // walk window [wend-128, wend)
            while (true) {
                const int wbase = wend - 128;
                const int i0 = wbase + lane, i1 = i0 + 32, i2 = i0 + 64, i3 = i0 + 96;
                unsigned st0, st1, st2, st3;
                float    v0,  v1,  v2,  v3;
                while (true) {
                    // Opportunistic aggregate publish while still walking.
                    if (!agg_published && f_agg != 0u) {
                        if (lane == 0)
                            st_status(&g_status[tile], pack_status(epoch, 1u, s_agg));
                        agg_published = true;
                    }
                    // Poll 4 descriptors per lane: 128-wide window, 1 round trip.
                    if (i0 >= 0) { unsigned long long w = ld_status(&g_status[i0]);
                        unsigned tg = (unsigned)(w >> 32);
                        st0 = ((tg >> 2) == epoch) ? (tg & 3u) : 0u;
                        v0 = __uint_as_float((unsigned)w); } else { st0 = 2u; v0 = 0.f; }
                    if (i1 >= 0) { unsigned long long w = ld_status(&g_status[i1]);
                        unsigned tg = (unsigned)(w >> 32);
                        st1 = ((tg >> 2) == epoch) ? (tg & 3u) : 0u;
                        v1 = __uint_as_float((unsigned)w); } else { st1 = 2u; v1 = 0.f; }
                    if (i2 >= 0) { unsigned long long w = ld_status(&g_status[i2]);
                        unsigned tg = (unsigned)(w >> 32);
                        st2 = ((tg >> 2) == epoch) ? (tg & 3u) : 0u;
                        v2 = __uint_as_float((unsigned)w); } else { st2 = 2u; v2 = 0.f; }
                    if (i3 >= 0) { unsigned long long w = ld_status(&g_status[i3]);
                        unsigned tg = (unsigned)(w >> 32);
                        st3 = ((tg >> 2) == epoch) ? (tg & 3u) : 0u;
                        v3 = __uint_as_float((unsigned)w); } else { st3 = 2u; v3 = 0.f; }
                    bool ok = (st0 != 0u) & (st1 != 0u) & (st2 != 0u) & (st3 != 0u);
                    if (__all_sync(FULL_MASK, ok)) break;
                }
                // Highest INCLUSIVE in the 128-window (rel index 0..127).
                unsigned b3 = __ballot_sync(FULL_MASK, st3 == 2u);
                unsigned b2 = __ballot_sync(FULL_MASK, st2 == 2u);
                unsigned b1 = __ballot_sync(FULL_MASK, st1 == 2u);
                unsigned b0 = __ballot_sync(FULL_MASK, st0 == 2u);
                int hi;
                if      (b3) hi = 96 + 31 - __clz(b3);
                else if (b2) hi = 64 + 31 - __clz(b2);
                else if (b1) hi = 32 + 31 - __clz(b1);
                else if (b0) hi =      31 - __clz(b0);
                else         hi = -1;

                float c;
                if (hi >= 0) {
                    c = ((lane      >= hi) ? v0 : 0.f)
                      + ((lane + 32 >= hi) ? v1 : 0.f)
                      + ((lane + 64 >= hi) ? v2 : 0.f)
                      + ((lane + 96 >= hi) ? v3 : 0.f);
                } else {
                    c = v0 + v1 + v2 + v3;   // all aggregates: consume window
                }
                #pragma unroll
                for (int o = 16; o > 0; o >>= 1)
                    c += __shfl_xor_sync(FULL_MASK, c, o);
                prefix += c;
                if (hi >= 0) break;
                wend = wbase;                // wbase > 0 here (else sentinels gave hi>=0)
            }
        }

        // Aggregate ready (usually already) -> publish INCLUSIVE; single publisher.
        while (f_agg == 0u) { }
        if (lane == 0) {
            st_status(&g_status[tile], pack_status(epoch, 2u, prefix + s_agg));
            s_prefix = prefix;
            __threadfence_block();
            f_prefix = 1u;                   // release data warps
        }
    }
}

extern "C" void kernel_launch(void* const* d_in, const int* in_sizes, int n_in,
                              void* d_out, int out_size) {
    const float* x = (const float*)d_in[0];
    float* out = (float*)d_out;
    int n = in_sizes[0];
    unsigned ntiles = (unsigned)((n + TILE - 1) / TILE);
    if (ntiles > MAX_TILES) ntiles = MAX_TILES;  // sized for the fixed N=2^25 problem

    scan_kernel<<<ntiles, BLOCK>>>(x, out, n, ntiles);
}